// round 17
// baseline (speedup 1.0000x reference)
#include <cuda_runtime.h>
#include <cuda_bf16.h>
#include <cuda_fp16.h>
#include <math.h>
#include <stdint.h>

#define T_TOK   16384
#define HS      1024
#define FFN     4096
#define NEXP    8
#define CAP     4096
#define NASSIGN (2*T_TOK)
#define SLOTS   (NEXP*CAP)

#if defined(__CUDA_ARCH_FEAT_SM103_ALL) || defined(__CUDA_ARCH_FEAT_SM100_ALL) || defined(__CUDA_ARCH_FEAT_SM101_ALL)
#define HAS_TCGEN05 1
#else
#define HAS_TCGEN05 0
#endif

// ---------------- static device scratch ----------------
// tcgen05 path layouts (pre-swizzled smem-image blocks):
//   A blocks: [e][m_tile(16)][kb][256 rows x 32 cols fp16, SW64] = 16KB each
//   B blocks: [e][n_tile]    [kb][256 rows x 32 cols fp16, SW64] = 16KB each
__device__ __half g_xb[(size_t)SLOTS*HS];
__device__ __half g_h [(size_t)SLOTS*FFN];
__device__ float  g_y [(size_t)SLOTS*HS];
__device__ __half g_w1t[(size_t)NEXP*FFN*HS];
__device__ __half g_w2t[(size_t)NEXP*HS*FFN];
__device__ __half g_w1 [(size_t)NEXP*HS*FFN];   // fallback row-major
__device__ __half g_w2 [(size_t)NEXP*FFN*HS];   // fallback row-major
__device__ int    g_top_e[NASSIGN];
__device__ float  g_top_w[NASSIGN];
__device__ int    g_dst_slot[NASSIGN];

// ---------------- helpers ----------------
__device__ __forceinline__ uint32_t smem_addr32(const void* p){
  return (uint32_t)__cvta_generic_to_shared(p);
}
__device__ __forceinline__ void cp16s(uint32_t dst, const void* src){
  asm volatile("cp.async.cg.shared.global [%0], [%1], 16;\n" :: "r"(dst), "l"(src));
}
__device__ __forceinline__ void cp_commit(){ asm volatile("cp.async.commit_group;\n"); }
template<int NW> __device__ __forceinline__ void cp_wait(){
  asm volatile("cp.async.wait_group %0;\n" :: "n"(NW));
}
__device__ __forceinline__ void ldsm4(uint32_t* r, const __half* p){
  uint32_t a = smem_addr32(p);
  asm volatile("ldmatrix.sync.aligned.m8n8.x4.shared.b16 {%0,%1,%2,%3}, [%4];\n"
    : "=r"(r[0]),"=r"(r[1]),"=r"(r[2]),"=r"(r[3]) : "r"(a));
}
__device__ __forceinline__ void ldsm4t(uint32_t* r, const __half* p){
  uint32_t a = smem_addr32(p);
  asm volatile("ldmatrix.sync.aligned.m8n8.x4.trans.shared.b16 {%0,%1,%2,%3}, [%4];\n"
    : "=r"(r[0]),"=r"(r[1]),"=r"(r[2]),"=r"(r[3]) : "r"(a));
}
__device__ __forceinline__ void mma_f16_hmma(float* c, const uint32_t* a, uint32_t b0, uint32_t b1){
  asm volatile("mma.sync.aligned.m16n8k16.row.col.f32.f16.f16.f32 "
    "{%0,%1,%2,%3}, {%4,%5,%6,%7}, {%8,%9}, {%0,%1,%2,%3};\n"
    : "+f"(c[0]),"+f"(c[1]),"+f"(c[2]),"+f"(c[3])
    : "r"(a[0]),"r"(a[1]),"r"(a[2]),"r"(a[3]), "r"(b0),"r"(b1));
}
__device__ __forceinline__ uint32_t sw64(uint32_t off){ return off ^ ((off >> 3) & 0x30); }

__device__ __forceinline__ float gelu_fast(float x){
  float t = x*x;
  float u = x*(0.7978845608f + 0.0356774081f*t);
  float th;
  asm("tanh.approx.f32 %0, %1;" : "=f"(th) : "f"(u));
  return 0.5f*__fmaf_rn(x, th, x);
}
__device__ __forceinline__ uint32_t elect_one(){
  uint32_t pred;
  asm volatile("{\n.reg .pred p;\nelect.sync _|p, 0xFFFFFFFF;\nselp.b32 %0, 1, 0, p;\n}" : "=r"(pred));
  return pred;
}
__device__ __forceinline__ void mbar_init(uint32_t a, uint32_t cnt){
  asm volatile("mbarrier.init.shared.b64 [%0], %1;" :: "r"(a), "r"(cnt) : "memory");
}
__device__ __forceinline__ void mbar_expect_tx(uint32_t a, uint32_t bytes){
  asm volatile("mbarrier.arrive.expect_tx.shared.b64 _, [%0], %1;" :: "r"(a), "r"(bytes) : "memory");
}
__device__ __forceinline__ void mbar_wait(uint32_t a, uint32_t parity){
  asm volatile("{\n.reg .pred P;\nLW%=:\nmbarrier.try_wait.parity.acquire.cta.shared::cta.b64 P, [%0], %1, 0x989680;\n@!P bra LW%=;\n}"
    :: "r"(a), "r"(parity) : "memory");
}
#if HAS_TCGEN05
__device__ __forceinline__ void bulkcp(uint32_t dst, const void* src, uint32_t bytes, uint32_t mbar){
  asm volatile("cp.async.bulk.shared::cluster.global.mbarrier::complete_tx::bytes [%0], [%1], %2, [%3];"
    :: "r"(dst), "l"(src), "r"(bytes), "r"(mbar) : "memory");
}
__device__ __forceinline__ void bulkcp_mc(uint32_t dst, const void* src, uint32_t bytes, uint32_t mbar, uint16_t mask){
  asm volatile("cp.async.bulk.shared::cluster.global.mbarrier::complete_tx::bytes.multicast::cluster [%0], [%1], %2, [%3], %4;"
    :: "r"(dst), "l"(src), "r"(bytes), "r"(mbar), "h"(mask) : "memory");
}
__device__ __forceinline__ uint32_t cl_rank(){
  uint32_t r; asm("mov.u32 %0, %%cluster_ctarank;" : "=r"(r)); return r;
}
__device__ __forceinline__ void mbar_arrive_rank0(uint32_t local_addr){
  asm volatile("{\n.reg .b32 rem;\nmapa.shared::cluster.u32 rem, %0, %1;\n"
               "mbarrier.arrive.shared::cluster.b64 _, [rem];\n}"
    :: "r"(local_addr), "r"(0) : "memory");
}
__device__ __forceinline__ void cluster_sync(){
  asm volatile("barrier.cluster.arrive.aligned;" ::: "memory");
  asm volatile("barrier.cluster.wait.aligned;" ::: "memory");
}
__device__ __forceinline__ void tcg_alloc(uint32_t dst_smem, uint32_t ncols){
  asm volatile("tcgen05.alloc.cta_group::1.sync.aligned.shared::cta.b32 [%0], %1;" :: "r"(dst_smem), "r"(ncols) : "memory");
}
__device__ __forceinline__ void tcg_dealloc(uint32_t tmem, uint32_t ncols){
  asm volatile("tcgen05.dealloc.cta_group::1.sync.aligned.b32 %0, %1;" :: "r"(tmem), "r"(ncols));
}
__device__ __forceinline__ void tcg_relinquish(){
  asm volatile("tcgen05.relinquish_alloc_permit.cta_group::1.sync.aligned;");
}
__device__ __forceinline__ void tcg_commit(uint32_t mbar){
  asm volatile("tcgen05.commit.cta_group::1.mbarrier::arrive::one.shared::cluster.b64 [%0];" :: "r"(mbar) : "memory");
}
__device__ __forceinline__ void tcg_fence_after(){
  asm volatile("tcgen05.fence::after_thread_sync;" ::: "memory");
}
__device__ __forceinline__ void mma_f16_ss(uint32_t d, uint64_t a, uint64_t b, uint32_t idesc, uint32_t en){
  asm volatile("{\n.reg .pred p;\nsetp.ne.u32 p, %4, 0;\n"
    "tcgen05.mma.cta_group::1.kind::f16 [%0], %1, %2, %3, {%5,%5,%5,%5}, p;\n}"
    :: "r"(d), "l"(a), "l"(b), "r"(idesc), "r"(en), "r"(0u) : "memory");
}
__device__ __forceinline__ void ldtm32(uint32_t* r, uint32_t addr){
  asm volatile("tcgen05.ld.sync.aligned.32x32b.x32.b32 "
    "{%0,%1,%2,%3,%4,%5,%6,%7,%8,%9,%10,%11,%12,%13,%14,%15,"
    "%16,%17,%18,%19,%20,%21,%22,%23,%24,%25,%26,%27,%28,%29,%30,%31}, [%32];"
    : "=r"(r[0]),"=r"(r[1]),"=r"(r[2]),"=r"(r[3]),"=r"(r[4]),"=r"(r[5]),"=r"(r[6]),"=r"(r[7]),
      "=r"(r[8]),"=r"(r[9]),"=r"(r[10]),"=r"(r[11]),"=r"(r[12]),"=r"(r[13]),"=r"(r[14]),"=r"(r[15]),
      "=r"(r[16]),"=r"(r[17]),"=r"(r[18]),"=r"(r[19]),"=r"(r[20]),"=r"(r[21]),"=r"(r[22]),"=r"(r[23]),
      "=r"(r[24]),"=r"(r[25]),"=r"(r[26]),"=r"(r[27]),"=r"(r[28]),"=r"(r[29]),"=r"(r[30]),"=r"(r[31])
    : "r"(addr));
}
__device__ __forceinline__ void tcg_wait_ld(){
  asm volatile("tcgen05.wait::ld.sync.aligned;" ::: "memory");
}
// SW64 K-major smem descriptor: layout=4, SBO=32 (8 rows x 64B atom), LBO=1
__device__ __forceinline__ uint64_t make_desc_sw64(uint32_t base_addr){
  const uint64_t BASE = (uint64_t(4) << 61) | (uint64_t(1) << 46) | (uint64_t(32) << 32) | (uint64_t(1) << 16);
  return BASE | ((uint64_t)(base_addr >> 4) & 0x3FFF);
}
#endif

// ---------------- router: fp32 logits + softmax + top-2 (one warp per token) ----------
__global__ void router_kernel(const float* __restrict__ x, const float* __restrict__ wr){
  int widx = (blockIdx.x * blockDim.x + threadIdx.x) >> 5;
  int lane = threadIdx.x & 31;
  if (widx >= T_TOK) return;
  const float4* xr = (const float4*)(x + (size_t)widx * HS);
  const float4* w4 = (const float4*)wr;
  float acc[NEXP];
  #pragma unroll
  for (int e=0;e<NEXP;e++) acc[e]=0.f;
  #pragma unroll
  for (int it=0; it<8; it++){
    int h4 = it*32 + lane;
    float4 xv = xr[h4];
    const float4* wrow = w4 + (size_t)h4*8;
    float4 w0a = wrow[0], w0b = wrow[1];
    float4 w1a = wrow[2], w1b = wrow[3];
    float4 w2a = wrow[4], w2b = wrow[5];
    float4 w3a = wrow[6], w3b = wrow[7];
    acc[0] = fmaf(xv.x, w0a.x, fmaf(xv.y, w1a.x, fmaf(xv.z, w2a.x, fmaf(xv.w, w3a.x, acc[0]))));
    acc[1] = fmaf(xv.x, w0a.y, fmaf(xv.y, w1a.y, fmaf(xv.z, w2a.y, fmaf(xv.w, w3a.y, acc[1]))));
    acc[2] = fmaf(xv.x, w0a.z, fmaf(xv.y, w1a.z, fmaf(xv.z, w2a.z, fmaf(xv.w, w3a.z, acc[2]))));
    acc[3] = fmaf(xv.x, w0a.w, fmaf(xv.y, w1a.w, fmaf(xv.z, w2a.w, fmaf(xv.w, w3a.w, acc[3]))));
    acc[4] = fmaf(xv.x, w0b.x, fmaf(xv.y, w1b.x, fmaf(xv.z, w2b.x, fmaf(xv.w, w3b.x, acc[4]))));
    acc[5] = fmaf(xv.x, w0b.y, fmaf(xv.y, w1b.y, fmaf(xv.z, w2b.y, fmaf(xv.w, w3b.y, acc[5]))));
    acc[6] = fmaf(xv.x, w0b.z, fmaf(xv.y, w1b.z, fmaf(xv.z, w2b.z, fmaf(xv.w, w3b.z, acc[6]))));
    acc[7] = fmaf(xv.x, w0b.w, fmaf(xv.y, w1b.w, fmaf(xv.z, w2b.w, fmaf(xv.w, w3b.w, acc[7]))));
  }
  #pragma unroll
  for (int off=16; off; off>>=1){
    #pragma unroll
    for (int e=0;e<NEXP;e++) acc[e] += __shfl_xor_sync(0xffffffffu, acc[e], off);
  }
  if (lane == 0){
    float m = acc[0];
    #pragma unroll
    for (int e=1;e<NEXP;e++) m = fmaxf(m, acc[e]);
    float ex[NEXP], s = 0.f;
    #pragma unroll
    for (int e=0;e<NEXP;e++){ ex[e] = __expf(acc[e]-m); s += ex[e]; }
    int e0 = 0; float b0 = acc[0];
    #pragma unroll
    for (int e=1;e<NEXP;e++) if (acc[e] > b0){ b0 = acc[e]; e0 = e; }
    int e1 = (e0==0) ? 1 : 0; float b1 = acc[e1];
    #pragma unroll
    for (int e=0;e<NEXP;e++) if (e != e0 && acc[e] > b1){ b1 = acc[e]; e1 = e; }
    float inv = 1.f/s;
    g_top_e[2*widx]   = e0;
    g_top_e[2*widx+1] = e1;
    g_top_w[2*widx]   = ex[e0]*inv;
    g_top_w[2*widx+1] = ex[e1]*inv;
  }
}

// ---------------- stable counting sort + capacity (hierarchical scan) ----------------
__global__ void __launch_bounds__(1024,1) scan_kernel(){
  __shared__ int wbase[32][NEXP];
  __shared__ int etot[NEXP];
  __shared__ int starts[NEXP];
  int t = threadIdx.x, lane = t & 31, w = t >> 5;
  const int i0 = t * 32;
  int e_loc[32];
  int cnt[NEXP];
  #pragma unroll
  for (int e=0;e<NEXP;e++) cnt[e]=0;
  #pragma unroll
  for (int j=0;j<32;j++){ e_loc[j] = g_top_e[i0+j]; cnt[e_loc[j]]++; }
  int excl[NEXP];
  #pragma unroll
  for (int e=0;e<NEXP;e++){
    int v = cnt[e], s = v;
    #pragma unroll
    for (int off=1; off<32; off<<=1){
      int n = __shfl_up_sync(0xffffffffu, s, off);
      if (lane >= off) s += n;
    }
    excl[e] = s - v;
    if (lane == 31) wbase[w][e] = s;
  }
  __syncthreads();
  if (w == 0){
    #pragma unroll
    for (int e=0;e<NEXP;e++){
      int v = wbase[lane][e], s = v;
      #pragma unroll
      for (int off=1; off<32; off<<=1){
        int n = __shfl_up_sync(0xffffffffu, s, off);
        if (lane >= off) s += n;
      }
      wbase[lane][e] = s - v;
      if (lane == 31) etot[e] = s;
    }
  }
  __syncthreads();
  if (t == 0){
    int run = 0;
    #pragma unroll
    for (int e=0;e<NEXP;e++){ starts[e] = run; run += etot[e]; }
  }
  __syncthreads();
  int base[NEXP];
  #pragma unroll
  for (int e=0;e<NEXP;e++) base[e] = starts[e] + wbase[w][e] + excl[e];
  #pragma unroll
  for (int j=0;j<32;j++){
    int e = e_loc[j];
    int pos = base[e]++;
    int r = pos - starts[e];
    g_dst_slot[i0+j] = (r < CAP) ? (e*CAP + r) : -1;
  }
}

// ---------------- fused prep, EXACT grid (128,32,20), block 256 ----------------
__global__ void prep_kernel(const float* __restrict__ x,
                            const float* __restrict__ w1,
                            const float* __restrict__ w2){
  if (blockIdx.z < 16){
#if HAS_TCGEN05
    __shared__ float tile[32][33];
    int which = blockIdx.z >= 8;
    int e = blockIdx.z & 7;
    const int K = which ? FFN : HS;
    const int N = which ? HS  : FFN;
    const int NT = N/256, KBn = K/32;
    const float* w = which ? w2 : w1;
    char* dstb = which ? (char*)g_w2t : (char*)g_w1t;
    int nb = which ? blockIdx.y : blockIdx.x;
    int kb = which ? blockIdx.x : blockIdx.y;
    int n0 = nb*32, k0 = kb*32;
    int tx = threadIdx.x & 31, ty = threadIdx.x >> 5;   // 32 x 8
    const float* in = w + (size_t)e*K*N;
    #pragma unroll
    for (int r=0;r<4;r++)
      tile[ty+8*r][tx] = in[(size_t)(k0+ty+8*r)*N + n0+tx];
    __syncthreads();
    #pragma unroll
    for (int r=0;r<4;r++){
      float v = tile[tx][ty+8*r];
      int n = n0 + ty + 8*r, k = k0 + tx;
      size_t blk = ((size_t)(e*NT + (n>>8)))*KBn + (k>>5);
      uint32_t inner = sw64((uint32_t)((n & 255)*64 + (k & 31)*2));
      *(__half*)(dstb + blk*16384 + inner) = __float2half_rn(v);
    }
#endif
    return;
  }
  // ---- gather ----
  int bid = (blockIdx.z - 16)*4096 + blockIdx.y*128 + blockIdx.x;
  int i = bid*2 + (threadIdx.x >> 7);
  int t128 = threadIdx.x & 127;
  int dst = g_dst_slot[i];
  if (dst < 0) return;
  const float4* src = (const float4*)(x + (size_t)(i>>1)*HS);
#if HAS_TCGEN05
  int e  = dst >> 12;
  int mt = (dst >> 8) & 15;
  int r  = dst & 255;
  char* ab = (char*)g_xb + (((size_t)(e*16 + mt))*32)*16384;
  float4 a = src[t128*2], b = src[t128*2+1];
  union { uint4 u; __half2 h[4]; } pk;
  pk.h[0] = __floats2half2_rn(a.x, a.y);
  pk.h[1] = __floats2half2_rn(a.z, a.w);
  pk.h[2] = __floats2half2_rn(b.x, b.y);
  pk.h[3] = __floats2half2_rn(b.z, b.w);
  int kb = t128 >> 2, c = t128 & 3;
  uint32_t inner = sw64((uint32_t)(r*64 + c*16));
  *(uint4*)(ab + (size_t)kb*16384 + inner) = pk.u;
#else
  __half* xb = g_xb + (size_t)dst*HS;
  for (int j = t128; j < HS/4; j += 128){
    float4 v = src[j];
    *(__half2*)&xb[j*4]   = __floats2half2_rn(v.x, v.y);
    *(__half2*)&xb[j*4+2] = __floats2half2_rn(v.z, v.w);
  }
#endif
}

// ---------------- HMMA-path weight convert fp32 -> fp16 ([E][K][N]) --------
__global__ void split_w_kernel(const float* __restrict__ w, int which){
#if !HAS_TCGEN05
  __half* dst = which ? g_w2 : g_w1;
  size_t i = (size_t)blockIdx.x*blockDim.x + threadIdx.x;
  const size_t n4 = (size_t)NEXP*HS*FFN/4;
  if (i >= n4) return;
  float4 v = ((const float4*)w)[i];
  *(__half2*)&dst[i*4]   = __floats2half2_rn(v.x, v.y);
  *(__half2*)&dst[i*4+2] = __floats2half2_rn(v.z, v.w);
#endif
}

// =====================================================================
// PATH A: tcgen05 fp16 GEMM, tile 256x256, K-chunk 32, 4-stage ring.
// Cluster of 4 m-tile CTAs sharing B via cp.async.bulk multicast:
//   rank 0 multicasts the 16KB B block to all 4 CTAs (L2 traffic /4);
//   each CTA loads its own 16KB A block.
// Cross-CTA buffer reuse gated by bfree[4] (count=4) on rank 0.
// =====================================================================
#define STAGEB 32768
#define GSMEM (4*STAGEB + 1024)

template<int PHASE>
__global__ void __launch_bounds__(256,1) __cluster_dims__(1,4,1) gemm_tc_kernel(){
#if HAS_TCGEN05
  constexpr int Kdim = (PHASE==1) ? HS  : FFN;
  constexpr int Ndim = (PHASE==1) ? FFN : HS;
  constexpr int NKB  = Kdim/32;
  constexpr int NT   = Ndim/256;
  const char* A_g = (const char*)((PHASE==1) ? g_xb  : g_h);
  const char* B_g = (const char*)((PHASE==1) ? g_w1t : g_w2t);

  extern __shared__ char dyn[];
  __shared__ uint64_t s_mbar[12];   // [0..3] full, [4..7] mma-done, [8..11] bfree (rank0)
  __shared__ uint32_t s_tptr;
  uint32_t sbase = (smem_addr32(dyn) + 1023u) & ~1023u;

  const int tid = threadIdx.x;
  const int wid = tid >> 5, lane = tid & 31;
  const int e = blockIdx.z, bx = blockIdx.x, by = blockIdx.y;
  const uint32_t rank = cl_rank();
  const size_t Ablk = ((size_t)(e*16 + by))*NKB;
  const size_t Bblk = ((size_t)(e*NT + bx))*NKB;

  uint32_t fullb[4], mmab[4], bfree[4];
  #pragma unroll
  for (int s=0;s<4;s++){
    fullb[s]=smem_addr32(&s_mbar[s]);
    mmab[s]=smem_addr32(&s_mbar[4+s]);
    bfree[s]=smem_addr32(&s_mbar[8+s]);
  }

  if (wid == 0) tcg_alloc(smem_addr32(&s_tptr), 512);
  if (tid == 0){
    #pragma unroll
    for (int s=0;s<4;s++){ mbar_init(fullb[s],1); mbar_init(mmab[s],1); mbar_init(bfree[s],4); }
  }
  __syncthreads();
  cluster_sync();                 // all mbarriers visible before any multicast
  const uint32_t tmem = s_tptr;
  const uint32_t idesc = (1u<<4) | ((256u>>3)<<17) | ((128u>>4)<<24);

  if (wid == 1 && elect_one()){
    // ---- loader thread ----
    #pragma unroll
    for (int s=0;s<4;s++){
      uint32_t st = sbase + s*STAGEB;
      mbar_expect_tx(fullb[s], STAGEB);
      bulkcp(st, A_g + (Ablk + s)*16384, 16384, fullb[s]);
      if (rank == 0)
        bulkcp_mc(st + 16384, B_g + (Bblk + s)*16384, 16384, fullb[s], (uint16_t)0xF);
    }
    int phm[4] = {0,0,0,0};
    int phb[4] = {0,0,0,0};
    for (int s = 4; s < NKB; s++){
      int pb = s & 3;
      mbar_wait(mmab[pb], phm[pb]); phm[pb] ^= 1;   // own mma(s-4) done
      mbar_arrive_rank0(bfree[pb]);                 // tell rank0 this CTA freed pb
      uint32_t st = sbase + pb*STAGEB;
      mbar_expect_tx(fullb[pb], STAGEB);
      bulkcp(st, A_g + (Ablk + s)*16384, 16384, fullb[pb]);
      if (rank == 0){
        mbar_wait(bfree[pb], phb[pb]); phb[pb] ^= 1;  // all 4 CTAs freed pb
        bulkcp_mc(st + 16384, B_g + (Bblk + s)*16384, 16384, fullb[pb], (uint16_t)0xF);
      }
    }
  } else if (wid == 0 && elect_one()){
    // ---- MMA thread ----
    for (int kb = 0; kb < NKB; kb++){
      int buf = kb & 3;
      mbar_wait(fullb[buf], (kb>>2)&1);
      uint32_t st = sbase + buf*STAGEB;
      uint64_t dB = make_desc_sw64(st + 16384);
      #pragma unroll
      for (int half=0; half<2; half++){
        uint64_t dA = make_desc_sw64(st + half*8192);
        uint32_t d  = tmem + half*256;
        #pragma unroll
        for (int ks=0; ks<2; ks++)
          mma_f16_ss(d, dA + ks*2, dB + ks*2, idesc, (kb==0 && ks==0) ? 0u : 1u);
      }
      tcg_commit(mmab[buf]);
    }
    mbar_wait(mmab[(NKB-1)&3], ((NKB/4)-1)&1);
  }
  __syncthreads();
  tcg_fence_after();

  {
    const int half = wid >> 2;
    const int r = half*128 + (wid & 3)*32 + lane;
    #pragma unroll
    for (int ch=0; ch<8; ch++){
      uint32_t rg[32];
      ldtm32(rg, tmem + half*256 + ch*32);
      tcg_wait_ld();
      if constexpr (PHASE==1){
        int kb2 = bx*8 + ch;
        char* dst = (char*)g_h + (((size_t)(e*16 + by))*(FFN/32) + kb2)*16384;
        uint32_t hp[16];
        #pragma unroll
        for (int j=0;j<32;j+=2){
          float g0 = gelu_fast(__uint_as_float(rg[j]));
          float g1 = gelu_fast(__uint_as_float(rg[j+1]));
          uint32_t p;
          asm("cvt.rn.f16x2.f32 %0, %1, %2;" : "=r"(p) : "f"(g1), "f"(g0));
          hp[j>>1] = p;
        }
        #pragma unroll
        for (int i=0;i<4;i++){
          uint32_t inner = sw64((uint32_t)(r*64 + i*16));
          *(uint4*)(dst + inner) = make_uint4(hp[i*4],hp[i*4+1],hp[i*4+2],hp[i*4+3]);
        }
      } else {
        int nc = bx*256 + ch*32;
        size_t o = ((size_t)e*CAP + by*256 + r)*HS + nc;
        #pragma unroll
        for (int j=0;j<32;j+=4){
          *(float4*)&g_y[o+j] = make_float4(__uint_as_float(rg[j]),  __uint_as_float(rg[j+1]),
                                            __uint_as_float(rg[j+2]),__uint_as_float(rg[j+3]));
        }
      }
    }
  }
  __syncthreads();
  if (wid == 0){
    tcg_relinquish();
    tcg_dealloc(tmem, 512);
  }
  cluster_sync();                 // no CTA exits while peers' multicasts/arrives in flight
#endif
}

// =====================================================================
// PATH B: HMMA mma.sync fp16 grouped GEMM (fallback, row-major layouts)
// =====================================================================
#define HSMEM (2*9472*2)
template<int PHASE>
__global__ void __launch_bounds__(512,1) gemm_split_kernel(){
#if !HAS_TCGEN05
  constexpr int K  = (PHASE==1) ? HS  : FFN;
  constexpr int N  = (PHASE==1) ? FFN : HS;
  constexpr int KB = K/32;
  const __half* __restrict__ A_g = (PHASE==1) ? g_xb : g_h;
  const __half* __restrict__ B_g = (PHASE==1) ? g_w1 : g_w2;

  extern __shared__ __align__(16) __half sm[];

  const int e  = blockIdx.z;
  const int m0 = blockIdx.y * 128;
  const int n0 = blockIdx.x * 128;
  const size_t Abase = (size_t)e*CAP*K;
  const size_t Bbase = (size_t)e*K*N;
  const size_t Cbase = (size_t)e*CAP*N;

  const int tid = threadIdx.x;
  const int warp = tid >> 5, lane = tid & 31;
  const int wm = warp >> 2, wn = warp & 3;
  const int ar = tid >> 2,  ac = (tid & 3)  * 8;
  const int br = tid >> 4,  bc = (tid & 15) * 8;

  float acc[2][4][4];
  #pragma unroll
  for (int i=0;i<2;i++)
    #pragma unroll
    for (int j=0;j<4;j++)
      #pragma unroll
      for (int k=0;k<4;k++) acc[i][j][k]=0.f;

  {
    __half* s = sm;
    cp16s(smem_addr32(s +        ar*40 + ac), A_g + Abase + (size_t)(m0+ar)*K + ac);
    cp16s(smem_addr32(s + 5120 + br*136 + bc), B_g + Bbase + (size_t)br*N + n0 + bc);
    cp_commit();
  }
  for (int kb=0; kb<KB; kb++){
    if (kb+1 < KB){
      const int k0 = (kb+1)*32;
      __half* s = sm + ((kb+1)&1)*9472;
      cp16s(smem_addr32(s +        ar*40 + ac), A_g + Abase + (size_t)(m0+ar)*K + k0 + ac);
      cp16s(smem_addr32(s + 5120 + br*136 + bc), B_g + Bbase + (size_t)(k0+br)*N + n0 + bc);
      cp_commit();
      cp_wait<1>();
    } else {
      cp_wait<0>();
    }
    __syncthreads();
    const __half* s = sm + (kb&1)*9472;
    #pragma unroll
    for (int ks=0; ks<2; ks++){
      uint32_t a[2][4];
      #pragma unroll
      for (int mt=0; mt<2; mt++){
        const __half* p = s + (wm*32 + mt*16 + (lane&15))*40 + ks*16 + (lane>>4)*8;
        ldsm4(a[mt], p);
      }
      uint32_t b[2][4];
      #pragma unroll
      for (int nh=0; nh<2; nh++){
        const __half* p = s + 5120 + (ks*16 + (lane&15))*136 + wn*32 + nh*16 + (lane>>4)*8;
        ldsm4t(b[nh], p);
      }
      #pragma unroll
      for (int mt=0; mt<2; mt++){
        #pragma unroll
        for (int nt=0; nt<4; nt++){
          const int nh = nt>>1, sb = (nt&1)*2;
          mma_f16_hmma(acc[mt][nt], a[mt], b[nh][sb], b[nh][sb+1]);
        }
      }
    }
    __syncthreads();
  }
  const int g = lane>>2, tg = lane&3;
  #pragma unroll
  for (int mt=0; mt<2; mt++){
    #pragma unroll
    for (int nt=0; nt<4; nt++){
      const int row = m0 + wm*32 + mt*16 + g;
      const int col = n0 + wn*32 + nt*8 + tg*2;
      float v0=acc[mt][nt][0], v1=acc[mt][nt][1], v2=acc[mt][nt][2], v3=acc[mt][nt][3];
      if constexpr (PHASE==1){
        v0=gelu_fast(v0); v1=gelu_fast(v1); v2=gelu_fast(v2); v3=gelu_fast(v3);
        size_t o  = Cbase + (size_t)row*N + col;
        size_t o2 = Cbase + (size_t)(row+8)*N + col;
        *(__half2*)&g_h[o]  = __floats2half2_rn(v0, v1);
        *(__half2*)&g_h[o2] = __floats2half2_rn(v2, v3);
      } else {
        *(float2*)&g_y[Cbase + (size_t)row*N + col]     = make_float2(v0,v1);
        *(float2*)&g_y[Cbase + (size_t)(row+8)*N + col] = make_float2(v2,v3);
      }
    }
  }
#endif
}

// ---------------- per-token weighted combine + bias ----------------
__global__ void scatter_kernel(const float* __restrict__ bias, float* __restrict__ out){
  int t = blockIdx.x;
  int s0 = g_dst_slot[2*t], s1 = g_dst_slot[2*t+1];
  float w0 = g_top_w[2*t], w1 = g_top_w[2*t+1];
  const float4* y0 = (const float4*)(g_y + (size_t)(s0 < 0 ? 0 : s0)*HS);
  const float4* y1 = (const float4*)(g_y + (size_t)(s1 < 0 ? 0 : s1)*HS);
  const float4* b4 = (const float4*)bias;
  float4* o = (float4*)(out + (size_t)t*HS);
  for (int j = threadIdx.x; j < HS/4; j += blockDim.x){
    float4 r = b4[j];
    if (s0 >= 0){ float4 v = y0[j]; r.x += w0*v.x; r.y += w0*v.y; r.z += w0*v.z; r.w += w0*v.w; }
    if (s1 >= 0){ float4 v = y1[j]; r.x += w1*v.x; r.y += w1*v.y; r.z += w1*v.z; r.w += w1*v.w; }
    o[j] = r;
  }
}

// ---------------- launcher ----------------
extern "C" void kernel_launch(void* const* d_in, const int* in_sizes, int n_in,
                              void* d_out, int out_size){
  const float* x    = (const float*)d_in[0];
  const float* wr   = (const float*)d_in[1];
  const float* w1   = (const float*)d_in[2];
  const float* w2   = (const float*)d_in[3];
  const float* bias = (const float*)d_in[4];
  float* out = (float*)d_out;

  cudaFuncSetAttribute(gemm_tc_kernel<1>, cudaFuncAttributeMaxDynamicSharedMemorySize, GSMEM);
  cudaFuncSetAttribute(gemm_tc_kernel<2>, cudaFuncAttributeMaxDynamicSharedMemorySize, GSMEM);
  cudaFuncSetAttribute(gemm_split_kernel<1>, cudaFuncAttributeMaxDynamicSharedMemorySize, HSMEM);
  cudaFuncSetAttribute(gemm_split_kernel<2>, cudaFuncAttributeMaxDynamicSharedMemorySize, HSMEM);

  cudaFuncAttributes fa{};
  cudaFuncGetAttributes(&fa, gemm_tc_kernel<1>);
  const bool tc = fa.numRegs > 32;

  router_kernel<<<T_TOK/8, 256>>>(x, wr);                               // 0
  scan_kernel<<<1, 1024>>>();                                           // 1
  prep_kernel<<<dim3(128,32,20), 256>>>(x, w1, w2);                     // 2
  if (tc){
    gemm_tc_kernel<1><<<dim3(FFN/256, CAP/256, NEXP), 256, GSMEM>>>();  // 3 <- profiled
    gemm_tc_kernel<2><<<dim3(HS/256,  CAP/256, NEXP), 256, GSMEM>>>();
  } else {
    const int n4 = NEXP*HS*FFN/4;
    split_w_kernel<<<(n4+255)/256, 256>>>(w1, 0);
    split_w_kernel<<<(n4+255)/256, 256>>>(w2, 1);
    gemm_split_kernel<1><<<dim3(FFN/128, CAP/128, NEXP), 512, HSMEM>>>();
    gemm_split_kernel<2><<<dim3(HS/128,  CAP/128, NEXP), 512, HSMEM>>>();
  }
  scatter_kernel<<<T_TOK, 128>>>(bias, out);
}